// round 3
// baseline (speedup 1.0000x reference)
#include <cuda_runtime.h>
#include <cuda_bf16.h>

#define NN 50000
#define NE 800000

typedef unsigned long long ull;

// ---------------- device scratch (no allocations allowed) ----------------
__device__ float g_agg_h[NN * 64];
__device__ float g_sum_t[NN * 3];
__device__ float g_cnt[NN];

__device__ __forceinline__ void red_add_v4(float* p, float a, float b, float c, float d) {
    asm volatile("red.global.add.v4.f32 [%0], {%1,%2,%3,%4};"
                 :: "l"(p), "f"(a), "f"(b), "f"(c), "f"(d) : "memory");
}
__device__ __forceinline__ ull pack2(float a, float b) {
    ull r; asm("mov.b64 %0, {%1,%2};" : "=l"(r) : "f"(a), "f"(b)); return r;
}
__device__ __forceinline__ ull ffma2(ull a, ull b, ull c) {
    ull d; asm("fma.rn.f32x2 %0, %1, %2, %3;" : "=l"(d) : "l"(a), "l"(b), "l"(c)); return d;
}
__device__ __forceinline__ float2 unpack2(ull v) {
    float2 r; asm("mov.b64 {%0,%1}, %2;" : "=f"(r.x), "=f"(r.y) : "l"(v)); return r;
}

// packed quarter-GEMV step for two edges: A/B are 8-ull (16-float) accumulators,
// wq points at this lane's 16-output quarter of the 64-wide weight row.
__device__ __forceinline__ void qstep(ull* A, ull* B, float xA, float xB, const float* wq) {
    const ull a = pack2(xA, xA);
    const ull b = pack2(xB, xB);
    const ulonglong2* w = reinterpret_cast<const ulonglong2*>(wq);
    #pragma unroll
    for (int t = 0; t < 4; t++) {
        const ulonglong2 wv = w[t];
        A[2*t]   = ffma2(a, wv.x, A[2*t]);
        A[2*t+1] = ffma2(a, wv.y, A[2*t+1]);
        B[2*t]   = ffma2(b, wv.x, B[2*t]);
        B[2*t+1] = ffma2(b, wv.y, B[2*t+1]);
    }
}

// ---------------- zero scratch (runs AFTER node kernel; globals start zeroed) ----
__global__ void zero_kernel() {
    const int total = NN * 64 + NN * 3 + NN;
    for (int i = blockIdx.x * blockDim.x + threadIdx.x; i < total; i += gridDim.x * blockDim.x) {
        if (i < NN * 64)               g_agg_h[i] = 0.f;
        else if (i < NN * 64 + NN * 3) g_sum_t[i - NN * 64] = 0.f;
        else                           g_cnt[i - NN * 64 - NN * 3] = 0.f;
    }
}

// ---------------- edge kernel (quad scheme: 4 lanes/edge-pair, 2 edges/lane) ----
// smem floats: weights 16704 | exchange 8 warps * 1152 = 9216  -> 25920 f = 103680 B
__global__ __launch_bounds__(256, 2)
void edge_kernel(const float* __restrict__ h, const float* __restrict__ coord,
                 const int* __restrict__ ei,
                 const float* __restrict__ We1, const float* __restrict__ be1,
                 const float* __restrict__ We2, const float* __restrict__ be2,
                 const float* __restrict__ Wc1, const float* __restrict__ bc1,
                 const float* __restrict__ Wc2, const float* __restrict__ bc2)
{
    extern __shared__ float s[];
    float* sWe1 = s;          // [129*64] = 8256
    float* sbe1 = s + 8256;   // [64]
    float* sWe2 = s + 8320;   // [4096]
    float* sbe2 = s + 12416;  // [64]
    float* sWc1 = s + 12480;  // [4096]
    float* sbc1 = s + 16576;  // [64]
    float* sWc2 = s + 16640;  // [64]
    float* xch  = s + 16704;  // 8 * 1152

    const int tid = threadIdx.x;
    for (int i = tid; i < 8256; i += 256) sWe1[i] = We1[i];
    for (int i = tid; i < 4096; i += 256) { sWe2[i] = We2[i]; sWc1[i] = Wc1[i]; }
    if (tid < 64) { sbe1[tid] = be1[tid]; sbe2[tid] = be2[tid]; sbc1[tid] = bc1[tid]; sWc2[tid] = Wc2[tid]; }
    __syncthreads();

    const int warp = tid >> 5, lane = tid & 31;
    const int q = lane & 3;     // output quarter (16 features)
    const int g = lane >> 2;    // edge-pair group within warp (0..7)
    float* xw = xch + warp * 1152;
    float* myx = xw + lane * 36;            // this lane's 32-float stash slot

    const long e0 = ((long)blockIdx.x * 8 + warp) * 16 + g * 2;   // edge A; edge B = e0+1
    const int rA = ei[e0],      rB = ei[e0 + 1];
    const int cA = ei[NE + e0], cB = ei[NE + e0 + 1];

    const float cdAx = coord[rA*3+0] - coord[cA*3+0];
    const float cdAy = coord[rA*3+1] - coord[cA*3+1];
    const float cdAz = coord[rA*3+2] - coord[cA*3+2];
    const float cdBx = coord[rB*3+0] - coord[cB*3+0];
    const float cdBy = coord[rB*3+1] - coord[cB*3+1];
    const float cdBz = coord[rB*3+2] - coord[cB*3+2];
    const float radA = cdAx*cdAx + cdAy*cdAy + cdAz*cdAz;
    const float radB = cdBx*cdBx + cdBy*cdBy + cdBz*cdBz;

    // ---- layer 1 ----
    ull aA[8], aB[8];
    {
        const float* b = sbe1 + q * 16;
        #pragma unroll
        for (int t = 0; t < 8; t++) { const ull v = pack2(b[2*t], b[2*t+1]); aA[t] = v; aB[t] = v; }
    }
    const float4* hrA = reinterpret_cast<const float4*>(h + (long)rA * 64);
    const float4* hrB = reinterpret_cast<const float4*>(h + (long)rB * 64);
    const float4* hcA = reinterpret_cast<const float4*>(h + (long)cA * 64);
    const float4* hcB = reinterpret_cast<const float4*>(h + (long)cB * 64);

    #pragma unroll 4
    for (int k4 = 0; k4 < 16; k4++) {
        const float4 xa = hrA[k4], xb = hrB[k4];
        const float* wb = sWe1 + k4 * 256 + q * 16;
        qstep(aA, aB, xa.x, xb.x, wb);
        qstep(aA, aB, xa.y, xb.y, wb + 64);
        qstep(aA, aB, xa.z, xb.z, wb + 128);
        qstep(aA, aB, xa.w, xb.w, wb + 192);
    }
    #pragma unroll 4
    for (int k4 = 0; k4 < 16; k4++) {
        const float4 xa = hcA[k4], xb = hcB[k4];
        const float* wb = sWe1 + 4096 + k4 * 256 + q * 16;
        qstep(aA, aB, xa.x, xb.x, wb);
        qstep(aA, aB, xa.y, xb.y, wb + 64);
        qstep(aA, aB, xa.z, xb.z, wb + 128);
        qstep(aA, aB, xa.w, xb.w, wb + 192);
    }
    qstep(aA, aB, radA, radB, sWe1 + 8192 + q * 16);   // radial row

    // stash relu(layer1) for warp-local exchange
    #pragma unroll
    for (int t = 0; t < 4; t++) {
        const float2 u = unpack2(aA[2*t]), v = unpack2(aA[2*t+1]);
        reinterpret_cast<float4*>(myx)[t] =
            make_float4(fmaxf(u.x,0.f), fmaxf(u.y,0.f), fmaxf(v.x,0.f), fmaxf(v.y,0.f));
        const float2 p = unpack2(aB[2*t]), r2 = unpack2(aB[2*t+1]);
        reinterpret_cast<float4*>(myx + 16)[t] =
            make_float4(fmaxf(p.x,0.f), fmaxf(p.y,0.f), fmaxf(r2.x,0.f), fmaxf(r2.y,0.f));
    }
    __syncwarp();

    // ---- layer 2 ----
    ull eA[8], eB[8];
    {
        const float* b = sbe2 + q * 16;
        #pragma unroll
        for (int t = 0; t < 8; t++) { const ull v = pack2(b[2*t], b[2*t+1]); eA[t] = v; eB[t] = v; }
    }
    #pragma unroll 4
    for (int k4 = 0; k4 < 16; k4++) {
        const float* xsrc = xw + (4*g + (k4 >> 2)) * 36 + (k4 & 3) * 4;
        const float4 xa = *reinterpret_cast<const float4*>(xsrc);
        const float4 xb = *reinterpret_cast<const float4*>(xsrc + 16);
        const float* wb = sWe2 + k4 * 256 + q * 16;
        qstep(eA, eB, xa.x, xb.x, wb);
        qstep(eA, eB, xa.y, xb.y, wb + 64);
        qstep(eA, eB, xa.z, xb.z, wb + 128);
        qstep(eA, eB, xa.w, xb.w, wb + 192);
    }
    __syncwarp();   // everyone done reading layer-1 stash

    // relu(ef): scatter to g_agg_h and stash for gate layer
    float* dstA = g_agg_h + (long)rA * 64 + q * 16;
    float* dstB = g_agg_h + (long)rB * 64 + q * 16;
    #pragma unroll
    for (int t = 0; t < 4; t++) {
        const float2 u = unpack2(eA[2*t]), v = unpack2(eA[2*t+1]);
        const float4 oa = make_float4(fmaxf(u.x,0.f), fmaxf(u.y,0.f), fmaxf(v.x,0.f), fmaxf(v.y,0.f));
        reinterpret_cast<float4*>(myx)[t] = oa;
        red_add_v4(dstA + 4*t, oa.x, oa.y, oa.z, oa.w);
        const float2 p = unpack2(eB[2*t]), r2 = unpack2(eB[2*t+1]);
        const float4 ob = make_float4(fmaxf(p.x,0.f), fmaxf(p.y,0.f), fmaxf(r2.x,0.f), fmaxf(r2.y,0.f));
        reinterpret_cast<float4*>(myx + 16)[t] = ob;
        red_add_v4(dstB + 4*t, ob.x, ob.y, ob.z, ob.w);
    }
    __syncwarp();

    // ---- gate hidden ----
    ull hA[8], hB[8];
    {
        const float* b = sbc1 + q * 16;
        #pragma unroll
        for (int t = 0; t < 8; t++) { const ull v = pack2(b[2*t], b[2*t+1]); hA[t] = v; hB[t] = v; }
    }
    #pragma unroll 4
    for (int k4 = 0; k4 < 16; k4++) {
        const float* xsrc = xw + (4*g + (k4 >> 2)) * 36 + (k4 & 3) * 4;
        const float4 xa = *reinterpret_cast<const float4*>(xsrc);
        const float4 xb = *reinterpret_cast<const float4*>(xsrc + 16);
        const float* wb = sWc1 + k4 * 256 + q * 16;
        qstep(hA, hB, xa.x, xb.x, wb);
        qstep(hA, hB, xa.y, xb.y, wb + 64);
        qstep(hA, hB, xa.z, xb.z, wb + 128);
        qstep(hA, hB, xa.w, xb.w, wb + 192);
    }

    // gate scalar: quarter-dot then quad butterfly reduce
    float gA = 0.f, gB = 0.f;
    {
        const float* w2 = sWc2 + q * 16;
        #pragma unroll
        for (int t = 0; t < 8; t++) {
            const float2 u = unpack2(hA[t]);
            gA += fmaxf(u.x,0.f) * w2[2*t] + fmaxf(u.y,0.f) * w2[2*t+1];
            const float2 v = unpack2(hB[t]);
            gB += fmaxf(v.x,0.f) * w2[2*t] + fmaxf(v.y,0.f) * w2[2*t+1];
        }
    }
    gA += __shfl_xor_sync(0xffffffffu, gA, 1);
    gA += __shfl_xor_sync(0xffffffffu, gA, 2);
    gB += __shfl_xor_sync(0xffffffffu, gB, 1);
    gB += __shfl_xor_sync(0xffffffffu, gB, 2);

    if (q == 0) {
        const float b2 = bc2[0];
        const float gateA = gA + b2, gateB = gB + b2;
        const float tAx = fminf(fmaxf(cdAx * gateA, -100.f), 100.f);
        const float tAy = fminf(fmaxf(cdAy * gateA, -100.f), 100.f);
        const float tAz = fminf(fmaxf(cdAz * gateA, -100.f), 100.f);
        const float tBx = fminf(fmaxf(cdBx * gateB, -100.f), 100.f);
        const float tBy = fminf(fmaxf(cdBy * gateB, -100.f), 100.f);
        const float tBz = fminf(fmaxf(cdBz * gateB, -100.f), 100.f);
        atomicAdd(&g_sum_t[rA*3+0], tAx); atomicAdd(&g_sum_t[rA*3+1], tAy); atomicAdd(&g_sum_t[rA*3+2], tAz);
        atomicAdd(&g_cnt[rA], 1.0f);
        atomicAdd(&g_sum_t[rB*3+0], tBx); atomicAdd(&g_sum_t[rB*3+1], tBy); atomicAdd(&g_sum_t[rB*3+2], tBz);
        atomicAdd(&g_cnt[rB], 1.0f);
    }
}

// ---------------- node kernel ----------------
__device__ __forceinline__ void gemv_row(ull* acc, ull xx, const float* wrow) {
    const ulonglong2* w = reinterpret_cast<const ulonglong2*>(wrow);
    #pragma unroll
    for (int j = 0; j < 16; j++) {
        const ulonglong2 wv = w[j];
        acc[2*j]   = ffma2(xx, wv.x, acc[2*j]);
        acc[2*j+1] = ffma2(xx, wv.y, acc[2*j+1]);
    }
}

__global__ __launch_bounds__(128, 2)
void node_kernel(const float* __restrict__ h, const float* __restrict__ coord,
                 const float* __restrict__ vel,
                 const float* __restrict__ Wn1, const float* __restrict__ bn1,
                 const float* __restrict__ Wn2, const float* __restrict__ bn2,
                 float* __restrict__ out)
{
    extern __shared__ float s[];
    float* sWn1 = s;          // 8192
    float* sbn1 = s + 8192;   // 64
    float* sWn2 = s + 8256;   // 4096
    float* sbn2 = s + 12352;  // 64

    const int tid = threadIdx.x;
    for (int i = tid; i < 8192; i += 128) sWn1[i] = Wn1[i];
    for (int i = tid; i < 4096; i += 128) sWn2[i] = Wn2[i];
    if (tid < 64) { sbn1[tid] = bn1[tid]; sbn2[tid] = bn2[tid]; }
    __syncthreads();

    const int n = blockIdx.x * 128 + tid;
    if (n >= NN) return;

    ull acc[32];
    {
        const ulonglong2* b = reinterpret_cast<const ulonglong2*>(sbn1);
        #pragma unroll
        for (int j = 0; j < 16; j++) { const ulonglong2 t = b[j]; acc[2*j] = t.x; acc[2*j+1] = t.y; }
    }
    const float4* hn = reinterpret_cast<const float4*>(h + (long)n * 64);
    const float4* an = reinterpret_cast<const float4*>(g_agg_h + (long)n * 64);

    #pragma unroll
    for (int half = 0; half < 2; half++) {
        const float4* src   = half ? an : hn;
        const float*  wbase = sWn1 + half * 64 * 64;
        for (int k4 = 0; k4 < 16; k4++) {
            const float4 x = src[k4];
            gemv_row(acc, pack2(x.x, x.x), wbase + (k4*4+0)*64);
            gemv_row(acc, pack2(x.y, x.y), wbase + (k4*4+1)*64);
            gemv_row(acc, pack2(x.z, x.z), wbase + (k4*4+2)*64);
            gemv_row(acc, pack2(x.w, x.w), wbase + (k4*4+3)*64);
        }
    }

    ull o2[32];
    {
        const ulonglong2* b = reinterpret_cast<const ulonglong2*>(sbn2);
        #pragma unroll
        for (int j = 0; j < 16; j++) { const ulonglong2 t = b[j]; o2[2*j] = t.x; o2[2*j+1] = t.y; }
    }
    for (int k2 = 0; k2 < 32; k2++) {
        const float2 a = unpack2(acc[k2]);
        const float x0 = fmaxf(a.x, 0.f), x1 = fmaxf(a.y, 0.f);
        gemv_row(o2, pack2(x0, x0), sWn2 + (2*k2+0)*64);
        gemv_row(o2, pack2(x1, x1), sWn2 + (2*k2+1)*64);
    }

    float4* outh = reinterpret_cast<float4*>(out + (long)n * 64);
    #pragma unroll
    for (int j = 0; j < 16; j++) {
        const float4 hv = hn[j];
        const float2 a = unpack2(o2[2*j]);
        const float2 bq = unpack2(o2[2*j+1]);
        outh[j] = make_float4(hv.x + a.x, hv.y + a.y, hv.z + bq.x, hv.w + bq.y);
    }

    const float cnt = g_cnt[n];
    const float inv = cnt > 0.f ? 1.f / cnt : 0.f;
    const float ax = g_sum_t[n*3+0] * inv;
    const float ay = g_sum_t[n*3+1] * inv;
    const float az = g_sum_t[n*3+2] * inv;
    const float invL = 0.125f;
    const float vx = vel[n*3+0] + ax * invL;
    const float vy = vel[n*3+1] + ay * invL;
    const float vz = vel[n*3+2] + az * invL;

    float* outc = out + (long)NN * 64;
    float* outv = outc + (long)NN * 3;
    outc[n*3+0] = coord[n*3+0] + vx * invL;
    outc[n*3+1] = coord[n*3+1] + vy * invL;
    outc[n*3+2] = coord[n*3+2] + vz * invL;
    outv[n*3+0] = vx; outv[n*3+1] = vy; outv[n*3+2] = vz;
}

// ---------------- launch ----------------
extern "C" void kernel_launch(void* const* d_in, const int* in_sizes, int n_in,
                              void* d_out, int out_size) {
    const float* h     = (const float*)d_in[0];
    const float* coord = (const float*)d_in[1];
    const float* vel   = (const float*)d_in[2];
    const int*   ei    = (const int*)d_in[4];
    const float* We1 = (const float*)d_in[5];
    const float* be1 = (const float*)d_in[6];
    const float* We2 = (const float*)d_in[7];
    const float* be2 = (const float*)d_in[8];
    const float* Wn1 = (const float*)d_in[9];
    const float* bn1 = (const float*)d_in[10];
    const float* Wn2 = (const float*)d_in[11];
    const float* bn2 = (const float*)d_in[12];
    const float* Wc1 = (const float*)d_in[13];
    const float* bc1 = (const float*)d_in[14];
    const float* Wc2 = (const float*)d_in[15];
    const float* bc2 = (const float*)d_in[16];
    float* out = (float*)d_out;

    cudaFuncSetAttribute(edge_kernel, cudaFuncAttributeMaxDynamicSharedMemorySize, 103680);
    cudaFuncSetAttribute(node_kernel, cudaFuncAttributeMaxDynamicSharedMemorySize, 49664);

    // scratch is zero at module load; zero_kernel (last) re-zeros it for the next replay
    edge_kernel<<<NE / 128, 256, 103680>>>(h, coord, ei,
                                           We1, be1, We2, be2, Wc1, bc1, Wc2, bc2);
    node_kernel<<<(NN + 127) / 128, 128, 49664>>>(h, coord, vel,
                                                  Wn1, bn1, Wn2, bn2, out);
    zero_kernel<<<296, 256>>>();
}